// round 1
// baseline (speedup 1.0000x reference)
#include <cuda_runtime.h>
#include <cuda_bf16.h>
#include <cstdint>

#define DI __device__ __forceinline__

// ---------------- problem constants ----------------
constexpr int BB = 4, SS_ = 2048, DD = 1024, CC = 32, NNc = 2, LLc = 128;
constexpr int HH = 16, DKk = 64, CHUNK_ = 64;
constexpr int HD = HH * DKk;              // 1024
constexpr int MQ = BB * CC * CHUNK_;      // 8192 query rows
constexpr int MKV = BB * CC * NNc * LLc;  // 32768 key rows
constexpr float EPSF = 1e-5f;
constexpr float SCALEF = 0.125f;          // 1/sqrt(64)

// ---------------- scratch (__device__ globals; no allocation allowed) -------
__device__ __nv_bfloat16 g_e  [(size_t)MKV * DD];
__device__ __nv_bfloat16 g_hsn[(size_t)MQ * DD];
__device__ __nv_bfloat16 g_wq [DD * HD];
__device__ __nv_bfloat16 g_wk [DD * HD];
__device__ __nv_bfloat16 g_wv [DD * HD];
__device__ __nv_bfloat16 g_wo [HD * DD];
__device__ __nv_bfloat16 g_q  [(size_t)MQ * HD];
__device__ __nv_bfloat16 g_k  [(size_t)MKV * HD];
__device__ __nv_bfloat16 g_v  [(size_t)MKV * HD];
__device__ __nv_bfloat16 g_ao [(size_t)MQ * HD];

// ---------------- PTX helpers ----------------
DI uint32_t smaddr(const void* p) { return (uint32_t)__cvta_generic_to_shared(p); }

DI void cp16(uint32_t dst, const void* src) {
    asm volatile("cp.async.cg.shared.global [%0], [%1], 16;\n" :: "r"(dst), "l"(src));
}
DI void cp_commit() { asm volatile("cp.async.commit_group;\n"); }
DI void cp_wait0()  { asm volatile("cp.async.wait_group 0;\n"); }

DI void ldsm4(uint32_t& r0, uint32_t& r1, uint32_t& r2, uint32_t& r3, uint32_t a) {
    asm volatile("ldmatrix.sync.aligned.m8n8.x4.shared.b16 {%0,%1,%2,%3}, [%4];"
                 : "=r"(r0), "=r"(r1), "=r"(r2), "=r"(r3) : "r"(a));
}
DI void ldsm4t(uint32_t& r0, uint32_t& r1, uint32_t& r2, uint32_t& r3, uint32_t a) {
    asm volatile("ldmatrix.sync.aligned.m8n8.x4.trans.shared.b16 {%0,%1,%2,%3}, [%4];"
                 : "=r"(r0), "=r"(r1), "=r"(r2), "=r"(r3) : "r"(a));
}
DI void ldsm2t(uint32_t& r0, uint32_t& r1, uint32_t a) {
    asm volatile("ldmatrix.sync.aligned.m8n8.x2.trans.shared.b16 {%0,%1}, [%2];"
                 : "=r"(r0), "=r"(r1) : "r"(a));
}
DI void mma16816(float* c, const uint32_t* a, const uint32_t* b) {
    asm volatile("mma.sync.aligned.m16n8k16.row.col.f32.bf16.bf16.f32 "
                 "{%0,%1,%2,%3},{%4,%5,%6,%7},{%8,%9},{%0,%1,%2,%3};"
                 : "+f"(c[0]), "+f"(c[1]), "+f"(c[2]), "+f"(c[3])
                 : "r"(a[0]), "r"(a[1]), "r"(a[2]), "r"(a[3]), "r"(b[0]), "r"(b[1]));
}

// ---------------- fp32 -> bf16 bulk convert ----------------
__global__ void k_f32_bf16(const float* __restrict__ src, __nv_bfloat16* __restrict__ dst, int n4) {
    int i = blockIdx.x * 256 + threadIdx.x;
    if (i < n4) {
        float4 v = reinterpret_cast<const float4*>(src)[i];
        __nv_bfloat162 a = __floats2bfloat162_rn(v.x, v.y);
        __nv_bfloat162 b = __floats2bfloat162_rn(v.z, v.w);
        uint2 o;
        o.x = *reinterpret_cast<uint32_t*>(&a);
        o.y = *reinterpret_cast<uint32_t*>(&b);
        reinterpret_cast<uint2*>(dst)[i] = o;
    }
}

// ---------------- LayerNorm of shifted h, zero-padded to 2048 rows ----------
__global__ __launch_bounds__(256) void k_ln(const float* __restrict__ h,
                                            const float* __restrict__ gamma,
                                            const float* __restrict__ beta,
                                            __nv_bfloat16* __restrict__ out) {
    int r = blockIdx.x;             // 0..8191  (b*2048 + rr)
    int b = r >> 11, rr = r & 2047;
    int t = threadIdx.x;
    __nv_bfloat16* dst = out + (size_t)r * DD + t * 4;
    if (rr >= 1985) {               // padded rows -> zeros
        uint2 z = {0u, 0u};
        *reinterpret_cast<uint2*>(dst) = z;
        return;
    }
    const float* src = h + ((size_t)(b << 11) + rr + (CHUNK_ - 1)) * DD;
    float4 x = *reinterpret_cast<const float4*>(src + t * 4);
    float s  = x.x + x.y + x.z + x.w;
    float sq = x.x * x.x + x.y * x.y + x.z * x.z + x.w * x.w;
    #pragma unroll
    for (int o = 16; o; o >>= 1) {
        s  += __shfl_xor_sync(0xffffffffu, s, o);
        sq += __shfl_xor_sync(0xffffffffu, sq, o);
    }
    __shared__ float rs_[8], rq_[8];
    __shared__ float mu_s, rstd_s;
    int w = t >> 5, ln = t & 31;
    if (!ln) { rs_[w] = s; rq_[w] = sq; }
    __syncthreads();
    if (t == 0) {
        float Sm = 0.f, Qm = 0.f;
        #pragma unroll
        for (int i = 0; i < 8; i++) { Sm += rs_[i]; Qm += rq_[i]; }
        float mu = Sm * (1.f / DD);
        float var = Qm * (1.f / DD) - mu * mu;
        mu_s = mu;
        rstd_s = rsqrtf(var + EPSF);
    }
    __syncthreads();
    float mu = mu_s, rstd = rstd_s;
    float4 g  = *reinterpret_cast<const float4*>(gamma + t * 4);
    float4 be = *reinterpret_cast<const float4*>(beta + t * 4);
    float y0 = (x.x - mu) * rstd * g.x + be.x;
    float y1 = (x.y - mu) * rstd * g.y + be.y;
    float y2 = (x.z - mu) * rstd * g.z + be.z;
    float y3 = (x.w - mu) * rstd * g.w + be.w;
    __nv_bfloat162 p0 = __floats2bfloat162_rn(y0, y1);
    __nv_bfloat162 p1 = __floats2bfloat162_rn(y2, y3);
    uint2 o;
    o.x = *reinterpret_cast<uint32_t*>(&p0);
    o.y = *reinterpret_cast<uint32_t*>(&p1);
    *reinterpret_cast<uint2*>(dst) = o;
}

// ---------------- bf16 GEMM: C[M,1024] = A[M,1024] @ Bw[1024,1024] + bias ---
// mode 0: write bf16 to Cb. mode 1: O-projection epilogue -> fp32 d_out with
// row shift (+63), residual add, skipping rr > 1984.
__global__ __launch_bounds__(256, 2) void k_gemm(const __nv_bfloat16* __restrict__ A,
                                                 const __nv_bfloat16* __restrict__ Bw,
                                                 __nv_bfloat16* __restrict__ Cb,
                                                 const float* __restrict__ bias,
                                                 float* __restrict__ outF,
                                                 const float* __restrict__ resid,
                                                 int mode) {
    __shared__ __nv_bfloat16 As[2][128 * 40];   // stride 40 (pad 8)
    __shared__ __nv_bfloat16 Bs[2][32 * 136];   // stride 136 (pad 8)
    int tid = threadIdx.x, wid = tid >> 5, lane = tid & 31;
    size_t mb = (size_t)blockIdx.x * 128;
    int nb = blockIdx.y * 128;

    float acc[4][4][4];
    #pragma unroll
    for (int a = 0; a < 4; a++)
        #pragma unroll
        for (int b = 0; b < 4; b++)
            #pragma unroll
            for (int c = 0; c < 4; c++) acc[a][b][c] = 0.f;

    const __nv_bfloat16* aptr = A + mb * 1024;
    const __nv_bfloat16* bptr = Bw + nb;

    auto issue = [&](int kt, int buf) {
        const __nv_bfloat16* as = aptr + kt * 32;
        #pragma unroll
        for (int i = 0; i < 2; i++) {
            int c = tid + 256 * i, r = c >> 2, cb = c & 3;
            cp16(smaddr(&As[buf][r * 40 + cb * 8]), as + (size_t)r * 1024 + cb * 8);
        }
        const __nv_bfloat16* bs = bptr + (size_t)kt * 32 * 1024;
        #pragma unroll
        for (int i = 0; i < 2; i++) {
            int c = tid + 256 * i, r = c >> 4, cb = c & 15;
            cp16(smaddr(&Bs[buf][r * 136 + cb * 8]), bs + (size_t)r * 1024 + cb * 8);
        }
        cp_commit();
    };

    issue(0, 0);
    cp_wait0();
    __syncthreads();

    int wm = (wid & 1) * 64, wn = (wid >> 1) * 32;
    for (int kt = 0; kt < 32; kt++) {
        int buf = kt & 1;
        if (kt < 31) issue(kt + 1, buf ^ 1);
        #pragma unroll
        for (int kk = 0; kk < 2; kk++) {
            int k0 = kk * 16;
            uint32_t af[4][4];
            #pragma unroll
            for (int mf = 0; mf < 4; mf++)
                ldsm4(af[mf][0], af[mf][1], af[mf][2], af[mf][3],
                      smaddr(&As[buf][(wm + mf * 16 + (lane & 15)) * 40 + k0 + (lane >> 4) * 8]));
            uint32_t bfr[4][2];
            #pragma unroll
            for (int nf2 = 0; nf2 < 2; nf2++) {
                uint32_t r0, r1, r2, r3;
                ldsm4t(r0, r1, r2, r3,
                       smaddr(&Bs[buf][(k0 + (lane & 15)) * 136 + wn + nf2 * 16 + (lane >> 4) * 8]));
                bfr[nf2 * 2][0] = r0; bfr[nf2 * 2][1] = r1;
                bfr[nf2 * 2 + 1][0] = r2; bfr[nf2 * 2 + 1][1] = r3;
            }
            #pragma unroll
            for (int mf = 0; mf < 4; mf++)
                #pragma unroll
                for (int nf = 0; nf < 4; nf++)
                    mma16816(acc[mf][nf], af[mf], bfr[nf]);
        }
        if (kt < 31) { cp_wait0(); __syncthreads(); }
    }

    int gid = lane >> 2, tig = lane & 3;
    if (mode == 0) {
        #pragma unroll
        for (int mf = 0; mf < 4; mf++)
            #pragma unroll
            for (int nf = 0; nf < 4; nf++) {
                size_t row = mb + wm + mf * 16 + gid;
                int col = nb + wn + nf * 8 + tig * 2;
                float2 bb = *reinterpret_cast<const float2*>(&bias[col]);
                __nv_bfloat162 o0 = __floats2bfloat162_rn(acc[mf][nf][0] + bb.x, acc[mf][nf][1] + bb.y);
                __nv_bfloat162 o1 = __floats2bfloat162_rn(acc[mf][nf][2] + bb.x, acc[mf][nf][3] + bb.y);
                *reinterpret_cast<__nv_bfloat162*>(&Cb[row * 1024 + col]) = o0;
                *reinterpret_cast<__nv_bfloat162*>(&Cb[(row + 8) * 1024 + col]) = o1;
            }
    } else {
        #pragma unroll
        for (int mf = 0; mf < 4; mf++)
            #pragma unroll
            for (int nf = 0; nf < 4; nf++) {
                int col = nb + wn + nf * 8 + tig * 2;
                float2 bb = *reinterpret_cast<const float2*>(&bias[col]);
                #pragma unroll
                for (int hr = 0; hr < 2; hr++) {
                    size_t row = mb + wm + mf * 16 + gid + hr * 8;
                    int b = (int)(row >> 11), rr = (int)(row & 2047);
                    if (rr < 1985) {
                        size_t o = (((size_t)b << 11) + rr + (CHUNK_ - 1)) * 1024 + col;
                        float2 rv = *reinterpret_cast<const float2*>(&resid[o]);
                        float2 ov = { acc[mf][nf][hr * 2] + bb.x + rv.x,
                                      acc[mf][nf][hr * 2 + 1] + bb.y + rv.y };
                        *reinterpret_cast<float2*>(&outF[o]) = ov;
                    }
                }
            }
    }
}

// ---------------- fused attention per (b*c, h): 64 q rows x 256 keys -------
constexpr int QS_STR = 72;    // bf16 elems
constexpr int KV_STR = 72;
constexpr int SS_STR = 260;   // f32 elems
constexpr int PS_STR = 264;   // bf16 elems
constexpr int OFF_Q  = 0;                       // 64*72*2   = 9216
constexpr int OFF_KV = 9216;                    // 256*72*2  = 36864
constexpr int OFF_S  = OFF_KV + 36864;          // 64*260*4  = 66560
constexpr int OFF_P  = OFF_S + 66560;           // 64*264*2  = 33792
constexpr int SMEM_ATT = OFF_P + 33792;         // 146432 bytes

__global__ __launch_bounds__(256, 1) void k_attn(const __nv_bfloat16* __restrict__ q,
                                                 const __nv_bfloat16* __restrict__ k,
                                                 const __nv_bfloat16* __restrict__ v,
                                                 __nv_bfloat16* __restrict__ ao) {
    extern __shared__ char sm[];
    __nv_bfloat16* q_s  = reinterpret_cast<__nv_bfloat16*>(sm + OFF_Q);
    __nv_bfloat16* kv_s = reinterpret_cast<__nv_bfloat16*>(sm + OFF_KV);
    float*         s_s  = reinterpret_cast<float*>(sm + OFF_S);
    __nv_bfloat16* p_s  = reinterpret_cast<__nv_bfloat16*>(sm + OFF_P);

    int bc = blockIdx.x, hh = blockIdx.y;
    int tid = threadIdx.x, wid = tid >> 5, lane = tid & 31;
    size_t qbase  = (size_t)bc * 64 * HD + hh * 64;
    size_t kvbase = (size_t)bc * 256 * HD + hh * 64;

    // load q (64x64) and k (256x64) tiles
    #pragma unroll
    for (int i = 0; i < 2; i++) {
        int c = tid + 256 * i, r = c >> 3, cb = c & 7;
        cp16(smaddr(q_s + r * QS_STR + cb * 8), q + qbase + (size_t)r * HD + cb * 8);
    }
    #pragma unroll
    for (int i = 0; i < 8; i++) {
        int c = tid + 256 * i, r = c >> 3, cb = c & 7;
        cp16(smaddr(kv_s + r * KV_STR + cb * 8), k + kvbase + (size_t)r * HD + cb * 8);
    }
    cp_commit();
    cp_wait0();
    __syncthreads();

    // ---- scores = q @ k^T * SCALE ; warp w owns key cols [w*32, w*32+32)
    {
        float acc[4][4][4];
        #pragma unroll
        for (int a = 0; a < 4; a++)
            #pragma unroll
            for (int b = 0; b < 4; b++)
                #pragma unroll
                for (int c = 0; c < 4; c++) acc[a][b][c] = 0.f;
        int jb = wid * 32;
        #pragma unroll
        for (int kk = 0; kk < 4; kk++) {
            int k0 = kk * 16;
            uint32_t af[4][4];
            #pragma unroll
            for (int mf = 0; mf < 4; mf++)
                ldsm4(af[mf][0], af[mf][1], af[mf][2], af[mf][3],
                      smaddr(q_s + (mf * 16 + (lane & 15)) * QS_STR + k0 + (lane >> 4) * 8));
            #pragma unroll
            for (int nn = 0; nn < 2; nn++) {
                uint32_t r0, r1, r2, r3;
                ldsm4(r0, r1, r2, r3,
                      smaddr(kv_s + (jb + nn * 16 + (lane & 15)) * KV_STR + k0 + (lane >> 4) * 8));
                uint32_t b0[2] = {r0, r2}, b1[2] = {r1, r3};
                #pragma unroll
                for (int mf = 0; mf < 4; mf++) {
                    mma16816(acc[mf][nn * 2], af[mf], b0);
                    mma16816(acc[mf][nn * 2 + 1], af[mf], b1);
                }
            }
        }
        int gid = lane >> 2, tig = lane & 3;
        #pragma unroll
        for (int mf = 0; mf < 4; mf++)
            #pragma unroll
            for (int nf = 0; nf < 4; nf++) {
                int row = mf * 16 + gid, col = jb + nf * 8 + tig * 2;
                float2 v0 = { acc[mf][nf][0] * SCALEF, acc[mf][nf][1] * SCALEF };
                float2 v1 = { acc[mf][nf][2] * SCALEF, acc[mf][nf][3] * SCALEF };
                *reinterpret_cast<float2*>(&s_s[row * SS_STR + col]) = v0;
                *reinterpret_cast<float2*>(&s_s[(row + 8) * SS_STR + col]) = v1;
            }
    }
    __syncthreads();

    // overlap V load with softmax
    #pragma unroll
    for (int i = 0; i < 8; i++) {
        int c = tid + 256 * i, r = c >> 3, cb = c & 7;
        cp16(smaddr(kv_s + r * KV_STR + cb * 8), v + kvbase + (size_t)r * HD + cb * 8);
    }
    cp_commit();

    // ---- softmax over 256 keys; warp w owns rows [w*8, w*8+8)
    #pragma unroll
    for (int ri = 0; ri < 8; ri++) {
        int r = wid * 8 + ri;
        float x[8];
        float m = -1e30f;
        #pragma unroll
        for (int i = 0; i < 8; i++) {
            x[i] = s_s[r * SS_STR + lane + 32 * i];
            m = fmaxf(m, x[i]);
        }
        #pragma unroll
        for (int o = 16; o; o >>= 1) m = fmaxf(m, __shfl_xor_sync(0xffffffffu, m, o));
        float sum = 0.f;
        #pragma unroll
        for (int i = 0; i < 8; i++) { x[i] = __expf(x[i] - m); sum += x[i]; }
        #pragma unroll
        for (int o = 16; o; o >>= 1) sum += __shfl_xor_sync(0xffffffffu, sum, o);
        float inv = 1.f / sum;
        #pragma unroll
        for (int i = 0; i < 8; i++)
            p_s[r * PS_STR + lane + 32 * i] = __float2bfloat16(x[i] * inv);
    }
    cp_wait0();
    __syncthreads();

    // ---- out = P @ V ; warp w owns out cols [w*8, w*8+8)
    {
        float acc[4][4];
        #pragma unroll
        for (int a = 0; a < 4; a++)
            #pragma unroll
            for (int b = 0; b < 4; b++) acc[a][b] = 0.f;
        int d0 = wid * 8;
        #pragma unroll
        for (int kt = 0; kt < 16; kt++) {
            uint32_t br[2];
            ldsm2t(br[0], br[1], smaddr(kv_s + (kt * 16 + (lane & 15)) * KV_STR + d0));
            #pragma unroll
            for (int mf = 0; mf < 4; mf++) {
                uint32_t a0, a1, a2, a3;
                ldsm4(a0, a1, a2, a3,
                      smaddr(p_s + (mf * 16 + (lane & 15)) * PS_STR + kt * 16 + (lane >> 4) * 8));
                uint32_t af[4] = {a0, a1, a2, a3};
                mma16816(acc[mf], af, br);
            }
        }
        int gid = lane >> 2, tig = lane & 3;
        #pragma unroll
        for (int mf = 0; mf < 4; mf++) {
            int row = mf * 16 + gid, col = d0 + tig * 2;
            __nv_bfloat162 o0 = __floats2bfloat162_rn(acc[mf][0], acc[mf][1]);
            __nv_bfloat162 o1 = __floats2bfloat162_rn(acc[mf][2], acc[mf][3]);
            *reinterpret_cast<__nv_bfloat162*>(&ao[((size_t)bc * 64 + row) * HD + hh * 64 + col]) = o0;
            *reinterpret_cast<__nv_bfloat162*>(&ao[((size_t)bc * 64 + row + 8) * HD + hh * 64 + col]) = o1;
        }
    }
}

// ---------------- out[:, 0:63] = residual only ----------------
__global__ void k_head(const float* __restrict__ h, float* __restrict__ out) {
    int i = blockIdx.x * 256 + threadIdx.x;   // float4 units over 4 * 63 * 1024 floats
    if (i < 64512) {
        int b = i / 16128, rem = i % 16128;   // 16128 = 63 * 256 float4 per batch
        size_t off = (size_t)b * 2048 * 256 + rem;
        reinterpret_cast<float4*>(out)[off] = reinterpret_cast<const float4*>(h)[off];
    }
}

// ---------------- launch ----------------
extern "C" void kernel_launch(void* const* d_in, const int* in_sizes, int n_in,
                              void* d_out, int out_size) {
    const float* h     = (const float*)d_in[0];
    const float* e     = (const float*)d_in[1];
    const float* Wq    = (const float*)d_in[2];
    const float* bq    = (const float*)d_in[3];
    const float* Wk    = (const float*)d_in[4];
    const float* bk    = (const float*)d_in[5];
    const float* Wv    = (const float*)d_in[6];
    const float* bv    = (const float*)d_in[7];
    const float* Wo    = (const float*)d_in[8];
    const float* bo    = (const float*)d_in[9];
    const float* gamma = (const float*)d_in[10];
    const float* beta  = (const float*)d_in[11];
    float* out = (float*)d_out;

    __nv_bfloat16 *p_e, *p_hsn, *p_wq, *p_wk, *p_wv, *p_wo, *p_q, *p_k, *p_v, *p_ao;
    cudaGetSymbolAddress((void**)&p_e,  g_e);
    cudaGetSymbolAddress((void**)&p_hsn, g_hsn);
    cudaGetSymbolAddress((void**)&p_wq, g_wq);
    cudaGetSymbolAddress((void**)&p_wk, g_wk);
    cudaGetSymbolAddress((void**)&p_wv, g_wv);
    cudaGetSymbolAddress((void**)&p_wo, g_wo);
    cudaGetSymbolAddress((void**)&p_q,  g_q);
    cudaGetSymbolAddress((void**)&p_k,  g_k);
    cudaGetSymbolAddress((void**)&p_v,  g_v);
    cudaGetSymbolAddress((void**)&p_ao, g_ao);

    cudaFuncSetAttribute(k_attn, cudaFuncAttributeMaxDynamicSharedMemorySize, SMEM_ATT);

    // convert weights + e to bf16
    k_f32_bf16<<<1024, 256>>>(Wq, p_wq, 262144);
    k_f32_bf16<<<1024, 256>>>(Wk, p_wk, 262144);
    k_f32_bf16<<<1024, 256>>>(Wv, p_wv, 262144);
    k_f32_bf16<<<1024, 256>>>(Wo, p_wo, 262144);
    k_f32_bf16<<<32768, 256>>>(e, p_e, 8388608);

    // layernorm (shift by 63, zero-pad tail)
    k_ln<<<8192, 256>>>(h, gamma, beta, p_hsn);

    // projections
    k_gemm<<<dim3(64, 8), 256>>>(p_hsn, p_wq, p_q, bq, nullptr, nullptr, 0);
    k_gemm<<<dim3(256, 8), 256>>>(p_e, p_wk, p_k, bk, nullptr, nullptr, 0);
    k_gemm<<<dim3(256, 8), 256>>>(p_e, p_wv, p_v, bv, nullptr, nullptr, 0);

    // fused attention
    k_attn<<<dim3(128, 16), 256, SMEM_ATT>>>(p_q, p_k, p_v, p_ao);

    // output projection + shift + residual
    k_gemm<<<dim3(64, 8), 256>>>(p_ao, p_wo, nullptr, bo, out, h, 1);

    // first 63 rows per batch = residual passthrough
    k_head<<<252, 256>>>(h, out);
}